// round 10
// baseline (speedup 1.0000x reference)
#include <cuda_runtime.h>

#define L        64
#define CHUNK    64
#define CPB      2          // obs-chunks per block
#define TPB      128
#define MAXQ     2048
#define MAXCH    16         // partial sets = ceil(NO / (CHUNK*CPB))

typedef unsigned long long ull;

// ---- scratch ( __device__ globals: allocation-free ) ----
__device__ __align__(16) float g_A[MAXQ * L];        // per-query affine part, ORIGINAL order
__device__ __align__(16) float g_B[MAXQ * L];        // per-obs affine part
__device__ __align__(16) float g_V[MAXQ * L];        // value-projected h_obs
__device__ float4 g_PQ[MAXQ];                        // query positions, SORTED order
__device__ int    g_perm[MAXQ];                      // sorted slot -> original query idx
__device__ float  g_psum[MAXCH * MAXQ];              // partial weight sums  (original q)
__device__ __align__(16) float g_pacc[MAXCH * MAXQ * L];  // partial value sums (original q)

// ---- packed f32x2 helpers ----
__device__ __forceinline__ ull pk_add(ull a, ull b) {
    ull r; asm("add.rn.f32x2 %0,%1,%2;" : "=l"(r) : "l"(a), "l"(b)); return r;
}
__device__ __forceinline__ ull pk_fma(ull a, ull b, ull c) {
    ull r; asm("fma.rn.f32x2 %0,%1,%2,%3;" : "=l"(r) : "l"(a), "l"(b), "l"(c)); return r;
}
union PK { ull u; float2 f; };
__device__ __forceinline__ ull pack2(float x, float y) { PK p; p.f.x = x; p.f.y = y; return p.u; }
__device__ __forceinline__ float2 unpack2(ull u) { PK p; p.u = u; return p.f; }

// ------------------------------------------------------------------
// Fused setup. Block 0: Morton counting sort of queries (8x8x8 cells)
// -> g_perm + g_PQ (sorted positions). Blocks >= 1: precompute
//   A[q,l] = b1[l] + pos_q[q] . (W1[0:3]+W1[6:9])        (ORIGINAL order)
//   B[o,l] =         pos_o[o] . (W1[3:6]-W1[6:9])
//   V[o,:] = bv + h_obs[o] @ Wv                          (packed f32x2)
// Sort scatter order is atomic-nondeterministic, but downstream math is
// keyed by original q and thread-assignment independent -> bitwise
// deterministic output.
// ------------------------------------------------------------------
__global__ void setup_kernel(const float* __restrict__ pos_q,
                             const float* __restrict__ pos_o,
                             const float* __restrict__ h_obs,
                             const float* __restrict__ W1,
                             const float* __restrict__ b1,
                             const float* __restrict__ Wv,
                             const float* __restrict__ bv,
                             int NQ, int NO)
{
    if (blockIdx.x == 0) {
        __shared__ int cid[MAXQ];
        __shared__ int hist[512];
        __shared__ int scanA[512];
        __shared__ int scanB[512];
        const int t = threadIdx.x;            // blockDim = 512
        hist[t] = 0;
        __syncthreads();

        for (int i = t; i < NQ; i += 512) {
            float x = pos_q[3*i], y = pos_q[3*i+1], z = pos_q[3*i+2];
            int xc = min(7, max(0, (int)(x * 8.f)));
            int yc = min(7, max(0, (int)(y * 8.f)));
            int zc = min(7, max(0, (int)(z * 8.f)));
            int m = 0;
            #pragma unroll
            for (int b = 0; b < 3; b++)
                m |= (((xc >> b) & 1) << (3*b)) | (((yc >> b) & 1) << (3*b + 1))
                   | (((zc >> b) & 1) << (3*b + 2));
            cid[i] = m;
            atomicAdd(&hist[m], 1);
        }
        __syncthreads();

        scanA[t] = hist[t];
        __syncthreads();
        int* src = scanA; int* dst = scanB;
        for (int d = 1; d < 512; d <<= 1) {
            dst[t] = src[t] + ((t >= d) ? src[t - d] : 0);
            __syncthreads();
            int* tmp = src; src = dst; dst = tmp;
        }
        src[t] -= hist[t];                    // exclusive offsets, in place
        __syncthreads();

        for (int i = t; i < NQ; i += 512) {
            int p = atomicAdd(&src[cid[i]], 1);
            g_perm[p] = i;
            g_PQ[p] = make_float4(pos_q[3*i], pos_q[3*i+1], pos_q[3*i+2], 0.f);
        }
        return;
    }

    int idx = (blockIdx.x - 1) * 512 + threadIdx.x;
    if (idx < NQ * L) {                       // A, original order
        int q = idx >> 6, l = idx & 63;
        float px = pos_q[q*3+0], py = pos_q[q*3+1], pz = pos_q[q*3+2];
        float a = b1[l];
        a = fmaf(px, W1[0*L+l] + W1[6*L+l], a);
        a = fmaf(py, W1[1*L+l] + W1[7*L+l], a);
        a = fmaf(pz, W1[2*L+l] + W1[8*L+l], a);
        g_A[idx] = a;
        return;
    }
    idx -= NQ * L;
    if (idx < NO * L) {                       // B
        int o = idx >> 6, l = idx & 63;
        float px = pos_o[o*3+0], py = pos_o[o*3+1], pz = pos_o[o*3+2];
        float b =      px * (W1[3*L+l] - W1[6*L+l]);
        b = fmaf(py, W1[4*L+l] - W1[7*L+l], b);
        b = fmaf(pz, W1[5*L+l] - W1[8*L+l], b);
        g_B[idx] = b;
        return;
    }
    idx -= NO * L;
    if (idx < NO * 32) {                      // V, packed pair of columns
        int o = idx >> 5, lp = idx & 31;
        const ull*    WvP = reinterpret_cast<const ull*>(Wv);
        const float4* h4  = reinterpret_cast<const float4*>(h_obs + o * L);
        float2 bvp = reinterpret_cast<const float2*>(bv)[lp];
        ull a0 = pack2(bvp.x, bvp.y), a1 = 0ull, a2 = 0ull, a3 = 0ull;
        #pragma unroll
        for (int k = 0; k < 16; k++) {
            float4 h = h4[k];
            a0 = pk_fma(pack2(h.x, h.x), WvP[(4*k+0)*32 + lp], a0);
            a1 = pk_fma(pack2(h.y, h.y), WvP[(4*k+1)*32 + lp], a1);
            a2 = pk_fma(pack2(h.z, h.z), WvP[(4*k+2)*32 + lp], a2);
            a3 = pk_fma(pack2(h.w, h.w), WvP[(4*k+3)*32 + lp], a3);
        }
        reinterpret_cast<ull*>(g_V)[o*32 + lp] = pk_add(pk_add(a0, a1), pk_add(a2, a3));
    }
}

// ------------------------------------------------------------------
// Main pairwise kernel. ONE THREAD = ONE (Morton-sorted) query, all 64
// latent dims. Packed f32x2 math; relu(x)*w == (x+|x|)*(w/2) exactly.
// Each block accumulates CPB consecutive obs-chunks (smem reloaded per
// chunk) before writing one partial set. Warp (32 spatially local
// queries) skips obs where every lane is outside the radius.
// ------------------------------------------------------------------
__global__ void __launch_bounds__(TPB, 3)
main_kernel(const float* __restrict__ pos_o,
            const float* __restrict__ W2,
            int NQ, int NO)
{
    __shared__ ulonglong2 Bs[CHUNK][16];   // 64 floats/row as 16x ulonglong2
    __shared__ ulonglong2 Vs[CHUNK][16];
    __shared__ ull        W2s[32];         // packed 0.5*W2
    __shared__ float      Ps[CHUNK * 3];

    const int tid = threadIdx.x;
    if (tid < 32)
        W2s[tid] = pack2(0.5f * W2[2*tid], 0.5f * W2[2*tid + 1]);

    int srt = blockIdx.x * TPB + tid;
    if (srt >= NQ) srt = NQ - 1;           // keep full warps; duplicate writes identical
    const int q = g_perm[srt];
    const float4 pq = g_PQ[srt];

    ull Aq[32];
    #pragma unroll
    for (int c = 0; c < 16; c++) {
        ulonglong2 t = reinterpret_cast<const ulonglong2*>(g_A)[q * 16 + c];
        Aq[2*c] = t.x; Aq[2*c+1] = t.y;
    }
    ull acc[32];
    #pragma unroll
    for (int c = 0; c < 32; c++) acc[c] = 0ull;
    float ssum = 0.f;

    const ull ABSM = 0x7FFFFFFF7FFFFFFFull;

    for (int cc = 0; cc < CPB; cc++) {
        const int o0 = (blockIdx.y * CPB + cc) * CHUNK;
        if (o0 >= NO) break;
        const int cnt = min(CHUNK, NO - o0);

        __syncthreads();                   // protect smem from previous iteration
        for (int i = tid; i < cnt * 16; i += TPB) {
            int j = i >> 4, c = i & 15;
            Bs[j][c] = reinterpret_cast<const ulonglong2*>(g_B)[(o0 + j) * 16 + c];
            Vs[j][c] = reinterpret_cast<const ulonglong2*>(g_V)[(o0 + j) * 16 + c];
        }
        for (int i = tid; i < cnt * 3; i += TPB)
            Ps[i] = pos_o[o0 * 3 + i];
        __syncthreads();

        for (int j = 0; j < cnt; j++) {
            const float dx = pq.x - Ps[3*j+0];
            const float dy = pq.y - Ps[3*j+1];
            const float dz = pq.z - Ps[3*j+2];
            const float d2 = fmaf(dx, dx, fmaf(dy, dy, dz * dz));
            if (__all_sync(0xFFFFFFFFu, d2 > 0.25f)) continue;

            ull lg0 = 0ull, lg1 = 0ull, lg2 = 0ull, lg3 = 0ull;
            #pragma unroll
            for (int c = 0; c < 16; c += 2) {
                const ulonglong2 ba = Bs[j][c];
                const ulonglong2 bb = Bs[j][c+1];
                ull x0 = pk_add(Aq[2*c+0], ba.x);
                ull x1 = pk_add(Aq[2*c+1], ba.y);
                ull x2 = pk_add(Aq[2*c+2], bb.x);
                ull x3 = pk_add(Aq[2*c+3], bb.y);
                x0 = pk_add(x0, x0 & ABSM);        // 2*relu
                x1 = pk_add(x1, x1 & ABSM);
                x2 = pk_add(x2, x2 & ABSM);
                x3 = pk_add(x3, x3 & ABSM);
                lg0 = pk_fma(x0, W2s[2*c+0], lg0);
                lg1 = pk_fma(x1, W2s[2*c+1], lg1);
                lg2 = pk_fma(x2, W2s[2*c+2], lg2);
                lg3 = pk_fma(x3, W2s[2*c+3], lg3);
            }
            float2 s = unpack2(pk_add(pk_add(lg0, lg1), pk_add(lg2, lg3)));
            const float wgt = (d2 <= 0.25f) ? __expf(s.x + s.y) : 0.f;
            ssum += wgt;
            const ull wp = pack2(wgt, wgt);
            #pragma unroll
            for (int c = 0; c < 16; c++) {
                const ulonglong2 v = Vs[j][c];
                acc[2*c+0] = pk_fma(wp, v.x, acc[2*c+0]);
                acc[2*c+1] = pk_fma(wp, v.y, acc[2*c+1]);
            }
        }
    }

    // partials keyed by ORIGINAL query index
    g_psum[blockIdx.y * MAXQ + q] = ssum;
    ulonglong2* pa = reinterpret_cast<ulonglong2*>(
        &g_pacc[((size_t)blockIdx.y * MAXQ + q) * L]);
    #pragma unroll
    for (int c = 0; c < 16; c++)
        pa[c] = make_ulonglong2(acc[2*c], acc[2*c+1]);
}

// ------------------------------------------------------------------
// Combine partial sets: out[q,l] = (sum_c acc) / (sum_c s)
// One thread per float4 output group; dual accumulators.
// ------------------------------------------------------------------
__global__ void reduce_kernel(float* __restrict__ out, int NQ, int nch)
{
    int idx = blockIdx.x * blockDim.x + threadIdx.x;   // float4 granularity
    if (idx >= NQ * 16) return;
    const int q = idx >> 4;
    const int g = idx & 15;

    float s = 0.f;
    for (int c = 0; c < nch; c++) s += g_psum[c * MAXQ + q];

    const float4* pa = reinterpret_cast<const float4*>(g_pacc);
    float4 a0 = make_float4(0.f, 0.f, 0.f, 0.f);
    float4 a1 = make_float4(0.f, 0.f, 0.f, 0.f);
    for (int c = 0; c + 1 < nch; c += 2) {
        float4 t0 = pa[((size_t)(c    ) * MAXQ + q) * 16 + g];
        float4 t1 = pa[((size_t)(c + 1) * MAXQ + q) * 16 + g];
        a0.x += t0.x; a0.y += t0.y; a0.z += t0.z; a0.w += t0.w;
        a1.x += t1.x; a1.y += t1.y; a1.z += t1.z; a1.w += t1.w;
    }
    if (nch & 1) {
        float4 t = pa[((size_t)(nch - 1) * MAXQ + q) * 16 + g];
        a0.x += t.x; a0.y += t.y; a0.z += t.z; a0.w += t.w;
    }
    const float inv = 1.f / s;
    float4 r;
    r.x = (a0.x + a1.x) * inv;
    r.y = (a0.y + a1.y) * inv;
    r.z = (a0.z + a1.z) * inv;
    r.w = (a0.w + a1.w) * inv;
    reinterpret_cast<float4*>(out)[idx] = r;
}

// ------------------------------------------------------------------
extern "C" void kernel_launch(void* const* d_in, const int* in_sizes, int n_in,
                              void* d_out, int out_size)
{
    const float* h_obs     = (const float*)d_in[0];
    // d_in[1] = x_obs (unused by the reference computation)
    const float* pos_obs   = (const float*)d_in[2];
    const float* pos_query = (const float*)d_in[3];
    const float* W1        = (const float*)d_in[4];
    const float* b1        = (const float*)d_in[5];
    const float* W2        = (const float*)d_in[6];
    // d_in[7] = b2 (constant shift, cancels in softmax)
    const float* Wv        = (const float*)d_in[8];
    const float* bv        = (const float*)d_in[9];

    const int NO = in_sizes[2] / 3;
    const int NQ = in_sizes[3] / 3;

    // fused sort (block 0) + prep (blocks 1..)
    const int prep_items = NQ * L + NO * L + NO * 32;
    const int setup_blocks = 1 + (prep_items + 511) / 512;
    setup_kernel<<<setup_blocks, 512>>>(pos_query, pos_obs, h_obs,
                                        W1, b1, Wv, bv, NQ, NO);

    const int nch = (NO + CHUNK * CPB - 1) / (CHUNK * CPB);   // partial sets
    dim3 grid((NQ + TPB - 1) / TPB, nch);
    main_kernel<<<grid, TPB>>>(pos_obs, W2, NQ, NO);

    reduce_kernel<<<(NQ * 16 + 255) / 256, 256>>>((float*)d_out, NQ, nch);
}

// round 11
// speedup vs baseline: 1.3450x; 1.3450x over previous
#include <cuda_runtime.h>

#define L        64
#define CHUNK    64
#define TPB      128
#define MAXQ     2048
#define MAXCH    32

typedef unsigned long long ull;

// ---- scratch ( __device__ globals: allocation-free ) ----
__device__ __align__(16) float g_A[MAXQ * L];        // per-query affine part, ORIGINAL order
__device__ __align__(16) float g_B[MAXQ * L];        // per-obs affine part
__device__ __align__(16) float g_V[MAXQ * L];        // value-projected h_obs
__device__ float4 g_PQ[MAXQ];                        // query positions, SORTED order
__device__ int    g_perm[MAXQ];                      // sorted slot -> original query idx
__device__ float  g_psum[MAXCH * MAXQ];              // partial weight sums  (original q)
__device__ __align__(16) float g_pacc[MAXCH * MAXQ * L];  // partial value sums (original q)

// ---- packed f32x2 helpers ----
__device__ __forceinline__ ull pk_add(ull a, ull b) {
    ull r; asm("add.rn.f32x2 %0,%1,%2;" : "=l"(r) : "l"(a), "l"(b)); return r;
}
__device__ __forceinline__ ull pk_fma(ull a, ull b, ull c) {
    ull r; asm("fma.rn.f32x2 %0,%1,%2,%3;" : "=l"(r) : "l"(a), "l"(b), "l"(c)); return r;
}
union PK { ull u; float2 f; };
__device__ __forceinline__ ull pack2(float x, float y) { PK p; p.f.x = x; p.f.y = y; return p.u; }
__device__ __forceinline__ float2 unpack2(ull u) { PK p; p.u = u; return p.f; }

// ------------------------------------------------------------------
// Fused setup. Block 0: Morton counting sort of queries (8x8x8 cells)
// -> g_perm + g_PQ. Blocks >= 1 (branch-pure per block; region sizes
// are multiples of 512):
//   A[q,l] = b1[l] + pos_q[q] . (W1[0:3]+W1[6:9])        (ORIGINAL order)
//   B[o,l] =         pos_o[o] . (W1[3:6]-W1[6:9])
//   V[o,:] = bv + h_obs[o] @ Wv          (packed f32x2, Wv staged in smem)
// Sort scatter order is atomic-nondeterministic, but downstream math is
// keyed by original q and thread-assignment independent -> bitwise
// deterministic output.
// ------------------------------------------------------------------
__global__ void setup_kernel(const float* __restrict__ pos_q,
                             const float* __restrict__ pos_o,
                             const float* __restrict__ h_obs,
                             const float* __restrict__ W1,
                             const float* __restrict__ b1,
                             const float* __restrict__ Wv,
                             const float* __restrict__ bv,
                             int NQ, int NO)
{
    if (blockIdx.x == 0) {
        __shared__ int cid[MAXQ];
        __shared__ int hist[512];
        __shared__ int scanA[512];
        __shared__ int scanB[512];
        const int t = threadIdx.x;            // blockDim = 512
        hist[t] = 0;
        __syncthreads();

        for (int i = t; i < NQ; i += 512) {
            float x = pos_q[3*i], y = pos_q[3*i+1], z = pos_q[3*i+2];
            int xc = min(7, max(0, (int)(x * 8.f)));
            int yc = min(7, max(0, (int)(y * 8.f)));
            int zc = min(7, max(0, (int)(z * 8.f)));
            int m = 0;
            #pragma unroll
            for (int b = 0; b < 3; b++)
                m |= (((xc >> b) & 1) << (3*b)) | (((yc >> b) & 1) << (3*b + 1))
                   | (((zc >> b) & 1) << (3*b + 2));
            cid[i] = m;
            atomicAdd(&hist[m], 1);
        }
        __syncthreads();

        scanA[t] = hist[t];
        __syncthreads();
        int* src = scanA; int* dst = scanB;
        for (int d = 1; d < 512; d <<= 1) {
            dst[t] = src[t] + ((t >= d) ? src[t - d] : 0);
            __syncthreads();
            int* tmp = src; src = dst; dst = tmp;
        }
        src[t] -= hist[t];                    // exclusive offsets, in place
        __syncthreads();

        for (int i = t; i < NQ; i += 512) {
            int p = atomicAdd(&src[cid[i]], 1);
            g_perm[p] = i;
            g_PQ[p] = make_float4(pos_q[3*i], pos_q[3*i+1], pos_q[3*i+2], 0.f);
        }
        return;
    }

    const int base = (blockIdx.x - 1) * 512;

    // ---- V branch: whole block lives in this region (offsets are 512-mult)
    if (base >= NQ * L + NO * L) {
        __shared__ ull WvS[L * 32];           // 64x64 floats = 2048 ull = 16KB
        const ull* WvP = reinterpret_cast<const ull*>(Wv);
        for (int i = threadIdx.x; i < L * 32; i += 512)
            WvS[i] = WvP[i];
        __syncthreads();

        int idx = base + threadIdx.x - (NQ * L + NO * L);
        if (idx >= NO * 32) return;
        int o = idx >> 5, lp = idx & 31;
        const float4* h4 = reinterpret_cast<const float4*>(h_obs + o * L);
        float2 bvp = reinterpret_cast<const float2*>(bv)[lp];
        ull a0 = pack2(bvp.x, bvp.y), a1 = 0ull, a2 = 0ull, a3 = 0ull;
        #pragma unroll
        for (int k = 0; k < 16; k++) {
            float4 h = h4[k];
            a0 = pk_fma(pack2(h.x, h.x), WvS[(4*k+0)*32 + lp], a0);
            a1 = pk_fma(pack2(h.y, h.y), WvS[(4*k+1)*32 + lp], a1);
            a2 = pk_fma(pack2(h.z, h.z), WvS[(4*k+2)*32 + lp], a2);
            a3 = pk_fma(pack2(h.w, h.w), WvS[(4*k+3)*32 + lp], a3);
        }
        reinterpret_cast<ull*>(g_V)[o*32 + lp] = pk_add(pk_add(a0, a1), pk_add(a2, a3));
        return;
    }

    int idx = base + threadIdx.x;
    if (idx < NQ * L) {                       // A, original order
        int q = idx >> 6, l = idx & 63;
        float px = pos_q[q*3+0], py = pos_q[q*3+1], pz = pos_q[q*3+2];
        float a = b1[l];
        a = fmaf(px, W1[0*L+l] + W1[6*L+l], a);
        a = fmaf(py, W1[1*L+l] + W1[7*L+l], a);
        a = fmaf(pz, W1[2*L+l] + W1[8*L+l], a);
        g_A[idx] = a;
        return;
    }
    idx -= NQ * L;
    if (idx < NO * L) {                       // B
        int o = idx >> 6, l = idx & 63;
        float px = pos_o[o*3+0], py = pos_o[o*3+1], pz = pos_o[o*3+2];
        float b =      px * (W1[3*L+l] - W1[6*L+l]);
        b = fmaf(py, W1[4*L+l] - W1[7*L+l], b);
        b = fmaf(pz, W1[5*L+l] - W1[8*L+l], b);
        g_B[idx] = b;
    }
}

// ------------------------------------------------------------------
// Main pairwise kernel (R6 structure: one thread = one sorted query,
// one obs-chunk per block, occupancy 2 so the 128-reg accumulator
// state never spills). Packed f32x2 math; relu(x)*w == (x+|x|)*(w/2).
// Warp (32 spatially local queries) skips obs where every lane is
// outside the radius.
// ------------------------------------------------------------------
__global__ void __launch_bounds__(TPB, 2)
main_kernel(const float* __restrict__ pos_o,
            const float* __restrict__ W2,
            int NQ, int NO)
{
    __shared__ ulonglong2 Bs[CHUNK][16];   // 64 floats/row as 16x ulonglong2
    __shared__ ulonglong2 Vs[CHUNK][16];
    __shared__ ull        W2s[32];         // packed 0.5*W2
    __shared__ float      Ps[CHUNK * 3];

    const int tid = threadIdx.x;
    const int o0  = blockIdx.y * CHUNK;
    const int cnt = min(CHUNK, NO - o0);

    for (int i = tid; i < cnt * 16; i += TPB) {
        int j = i >> 4, c = i & 15;
        Bs[j][c] = reinterpret_cast<const ulonglong2*>(g_B)[(o0 + j) * 16 + c];
        Vs[j][c] = reinterpret_cast<const ulonglong2*>(g_V)[(o0 + j) * 16 + c];
    }
    for (int i = tid; i < cnt * 3; i += TPB)
        Ps[i] = pos_o[o0 * 3 + i];
    if (tid < 32)
        W2s[tid] = pack2(0.5f * W2[2*tid], 0.5f * W2[2*tid + 1]);
    __syncthreads();

    int srt = blockIdx.x * TPB + tid;
    if (srt >= NQ) srt = NQ - 1;           // keep full warps; duplicate writes identical
    const int q = g_perm[srt];
    const float4 pq = g_PQ[srt];

    ull Aq[32];
    #pragma unroll
    for (int c = 0; c < 16; c++) {
        ulonglong2 t = reinterpret_cast<const ulonglong2*>(g_A)[q * 16 + c];
        Aq[2*c] = t.x; Aq[2*c+1] = t.y;
    }
    ull acc[32];
    #pragma unroll
    for (int c = 0; c < 32; c++) acc[c] = 0ull;
    float ssum = 0.f;

    const ull ABSM = 0x7FFFFFFF7FFFFFFFull;

    for (int j = 0; j < cnt; j++) {
        const float dx = pq.x - Ps[3*j+0];
        const float dy = pq.y - Ps[3*j+1];
        const float dz = pq.z - Ps[3*j+2];
        const float d2 = fmaf(dx, dx, fmaf(dy, dy, dz * dz));
        if (__all_sync(0xFFFFFFFFu, d2 > 0.25f)) continue;

        ull lg0 = 0ull, lg1 = 0ull, lg2 = 0ull, lg3 = 0ull;
        #pragma unroll
        for (int c = 0; c < 16; c += 2) {
            const ulonglong2 ba = Bs[j][c];
            const ulonglong2 bb = Bs[j][c+1];
            ull x0 = pk_add(Aq[2*c+0], ba.x);
            ull x1 = pk_add(Aq[2*c+1], ba.y);
            ull x2 = pk_add(Aq[2*c+2], bb.x);
            ull x3 = pk_add(Aq[2*c+3], bb.y);
            x0 = pk_add(x0, x0 & ABSM);        // 2*relu
            x1 = pk_add(x1, x1 & ABSM);
            x2 = pk_add(x2, x2 & ABSM);
            x3 = pk_add(x3, x3 & ABSM);
            lg0 = pk_fma(x0, W2s[2*c+0], lg0);
            lg1 = pk_fma(x1, W2s[2*c+1], lg1);
            lg2 = pk_fma(x2, W2s[2*c+2], lg2);
            lg3 = pk_fma(x3, W2s[2*c+3], lg3);
        }
        float2 s = unpack2(pk_add(pk_add(lg0, lg1), pk_add(lg2, lg3)));
        const float wgt = (d2 <= 0.25f) ? __expf(s.x + s.y) : 0.f;
        ssum += wgt;
        const ull wp = pack2(wgt, wgt);
        #pragma unroll
        for (int c = 0; c < 16; c++) {
            const ulonglong2 v = Vs[j][c];
            acc[2*c+0] = pk_fma(wp, v.x, acc[2*c+0]);
            acc[2*c+1] = pk_fma(wp, v.y, acc[2*c+1]);
        }
    }

    // partials keyed by ORIGINAL query index
    g_psum[blockIdx.y * MAXQ + q] = ssum;
    ulonglong2* pa = reinterpret_cast<ulonglong2*>(
        &g_pacc[((size_t)blockIdx.y * MAXQ + q) * L]);
    #pragma unroll
    for (int c = 0; c < 16; c++)
        pa[c] = make_ulonglong2(acc[2*c], acc[2*c+1]);
}

// ------------------------------------------------------------------
// Combine partial sets: out[q,l] = (sum_c acc) / (sum_c s)
// One thread per float4 output group; dual accumulators.
// ------------------------------------------------------------------
__global__ void reduce_kernel(float* __restrict__ out, int NQ, int nch)
{
    int idx = blockIdx.x * blockDim.x + threadIdx.x;   // float4 granularity
    if (idx >= NQ * 16) return;
    const int q = idx >> 4;
    const int g = idx & 15;

    float s = 0.f;
    for (int c = 0; c < nch; c++) s += g_psum[c * MAXQ + q];

    const float4* pa = reinterpret_cast<const float4*>(g_pacc);
    float4 a0 = make_float4(0.f, 0.f, 0.f, 0.f);
    float4 a1 = make_float4(0.f, 0.f, 0.f, 0.f);
    for (int c = 0; c + 1 < nch; c += 2) {
        float4 t0 = pa[((size_t)(c    ) * MAXQ + q) * 16 + g];
        float4 t1 = pa[((size_t)(c + 1) * MAXQ + q) * 16 + g];
        a0.x += t0.x; a0.y += t0.y; a0.z += t0.z; a0.w += t0.w;
        a1.x += t1.x; a1.y += t1.y; a1.z += t1.z; a1.w += t1.w;
    }
    if (nch & 1) {
        float4 t = pa[((size_t)(nch - 1) * MAXQ + q) * 16 + g];
        a0.x += t.x; a0.y += t.y; a0.z += t.z; a0.w += t.w;
    }
    const float inv = 1.f / s;
    float4 r;
    r.x = (a0.x + a1.x) * inv;
    r.y = (a0.y + a1.y) * inv;
    r.z = (a0.z + a1.z) * inv;
    r.w = (a0.w + a1.w) * inv;
    reinterpret_cast<float4*>(out)[idx] = r;
}

// ------------------------------------------------------------------
extern "C" void kernel_launch(void* const* d_in, const int* in_sizes, int n_in,
                              void* d_out, int out_size)
{
    const float* h_obs     = (const float*)d_in[0];
    // d_in[1] = x_obs (unused by the reference computation)
    const float* pos_obs   = (const float*)d_in[2];
    const float* pos_query = (const float*)d_in[3];
    const float* W1        = (const float*)d_in[4];
    const float* b1        = (const float*)d_in[5];
    const float* W2        = (const float*)d_in[6];
    // d_in[7] = b2 (constant shift, cancels in softmax)
    const float* Wv        = (const float*)d_in[8];
    const float* bv        = (const float*)d_in[9];

    const int NO = in_sizes[2] / 3;
    const int NQ = in_sizes[3] / 3;

    // fused sort (block 0) + prep (blocks 1..)
    const int prep_items = NQ * L + NO * L + NO * 32;
    const int setup_blocks = 1 + (prep_items + 511) / 512;
    setup_kernel<<<setup_blocks, 512>>>(pos_query, pos_obs, h_obs,
                                        W1, b1, Wv, bv, NQ, NO);

    const int nch = (NO + CHUNK - 1) / CHUNK;   // partial sets (=32)
    dim3 grid((NQ + TPB - 1) / TPB, nch);
    main_kernel<<<grid, TPB>>>(pos_obs, W2, NQ, NO);

    reduce_kernel<<<(NQ * 16 + 255) / 256, 256>>>((float*)d_out, NQ, nch);
}

// round 12
// speedup vs baseline: 1.3475x; 1.0018x over previous
#include <cuda_runtime.h>

#define L        64
#define CHUNK    64
#define TPB      128
#define MAXQ     2048
#define MAXCH    32

typedef unsigned long long ull;

// ---- scratch ( __device__ globals: allocation-free ) ----
__device__ __align__(16) float g_A[MAXQ * L];        // per-query affine part, ORIGINAL order
__device__ __align__(16) float g_B[MAXQ * L];        // per-obs affine part
__device__ __align__(16) float g_V[MAXQ * L];        // value-projected h_obs
__device__ float4 g_PQ[MAXQ];                        // query positions, SORTED order
__device__ int    g_perm[MAXQ];                      // sorted slot -> original query idx
__device__ float  g_psum[MAXCH * MAXQ];              // partial weight sums  (original q)
__device__ __align__(16) float g_pacc[MAXCH * MAXQ * L];  // partial value sums (original q)

// ---- packed f32x2 helpers ----
__device__ __forceinline__ ull pk_add(ull a, ull b) {
    ull r; asm("add.rn.f32x2 %0,%1,%2;" : "=l"(r) : "l"(a), "l"(b)); return r;
}
__device__ __forceinline__ ull pk_fma(ull a, ull b, ull c) {
    ull r; asm("fma.rn.f32x2 %0,%1,%2,%3;" : "=l"(r) : "l"(a), "l"(b), "l"(c)); return r;
}
union PK { ull u; float2 f; };
__device__ __forceinline__ ull pack2(float x, float y) { PK p; p.f.x = x; p.f.y = y; return p.u; }
__device__ __forceinline__ float2 unpack2(ull u) { PK p; p.u = u; return p.f; }

// ------------------------------------------------------------------
// Fused setup. Block 0: Morton counting sort of queries (8x8x8 cells)
// -> g_perm + g_PQ. Blocks >= 1 (branch-pure per block; region sizes
// are multiples of 512):
//   A[q,l] = b1[l] + pos_q[q] . (W1[0:3]+W1[6:9])        (ORIGINAL order)
//   B[o,l] =         pos_o[o] . (W1[3:6]-W1[6:9])
//   V[o,:] = bv + h_obs[o] @ Wv          (packed f32x2, Wv staged in smem)
// Sort scatter order is atomic-nondeterministic, but downstream math is
// keyed by original q and thread-assignment independent -> bitwise
// deterministic output.
// ------------------------------------------------------------------
__global__ void setup_kernel(const float* __restrict__ pos_q,
                             const float* __restrict__ pos_o,
                             const float* __restrict__ h_obs,
                             const float* __restrict__ W1,
                             const float* __restrict__ b1,
                             const float* __restrict__ Wv,
                             const float* __restrict__ bv,
                             int NQ, int NO)
{
    if (blockIdx.x == 0) {
        __shared__ int cid[MAXQ];
        __shared__ int hist[512];
        __shared__ int scanA[512];
        __shared__ int scanB[512];
        const int t = threadIdx.x;            // blockDim = 512
        hist[t] = 0;
        __syncthreads();

        for (int i = t; i < NQ; i += 512) {
            float x = pos_q[3*i], y = pos_q[3*i+1], z = pos_q[3*i+2];
            int xc = min(7, max(0, (int)(x * 8.f)));
            int yc = min(7, max(0, (int)(y * 8.f)));
            int zc = min(7, max(0, (int)(z * 8.f)));
            int m = 0;
            #pragma unroll
            for (int b = 0; b < 3; b++)
                m |= (((xc >> b) & 1) << (3*b)) | (((yc >> b) & 1) << (3*b + 1))
                   | (((zc >> b) & 1) << (3*b + 2));
            cid[i] = m;
            atomicAdd(&hist[m], 1);
        }
        __syncthreads();

        scanA[t] = hist[t];
        __syncthreads();
        int* src = scanA; int* dst = scanB;
        for (int d = 1; d < 512; d <<= 1) {
            dst[t] = src[t] + ((t >= d) ? src[t - d] : 0);
            __syncthreads();
            int* tmp = src; src = dst; dst = tmp;
        }
        src[t] -= hist[t];                    // exclusive offsets, in place
        __syncthreads();

        for (int i = t; i < NQ; i += 512) {
            int p = atomicAdd(&src[cid[i]], 1);
            g_perm[p] = i;
            g_PQ[p] = make_float4(pos_q[3*i], pos_q[3*i+1], pos_q[3*i+2], 0.f);
        }
        return;
    }

    const int base = (blockIdx.x - 1) * 512;

    // ---- V branch: whole block lives in this region (offsets are 512-mult)
    if (base >= NQ * L + NO * L) {
        __shared__ ull WvS[L * 32];           // 64x64 floats = 2048 ull = 16KB
        const ull* WvP = reinterpret_cast<const ull*>(Wv);
        for (int i = threadIdx.x; i < L * 32; i += 512)
            WvS[i] = WvP[i];
        __syncthreads();

        int idx = base + threadIdx.x - (NQ * L + NO * L);
        if (idx >= NO * 32) return;
        int o = idx >> 5, lp = idx & 31;
        const float4* h4 = reinterpret_cast<const float4*>(h_obs + o * L);
        float2 bvp = reinterpret_cast<const float2*>(bv)[lp];
        ull a0 = pack2(bvp.x, bvp.y), a1 = 0ull, a2 = 0ull, a3 = 0ull;
        #pragma unroll
        for (int k = 0; k < 16; k++) {
            float4 h = h4[k];
            a0 = pk_fma(pack2(h.x, h.x), WvS[(4*k+0)*32 + lp], a0);
            a1 = pk_fma(pack2(h.y, h.y), WvS[(4*k+1)*32 + lp], a1);
            a2 = pk_fma(pack2(h.z, h.z), WvS[(4*k+2)*32 + lp], a2);
            a3 = pk_fma(pack2(h.w, h.w), WvS[(4*k+3)*32 + lp], a3);
        }
        reinterpret_cast<ull*>(g_V)[o*32 + lp] = pk_add(pk_add(a0, a1), pk_add(a2, a3));
        return;
    }

    int idx = base + threadIdx.x;
    if (idx < NQ * L) {                       // A, original order
        int q = idx >> 6, l = idx & 63;
        float px = pos_q[q*3+0], py = pos_q[q*3+1], pz = pos_q[q*3+2];
        float a = b1[l];
        a = fmaf(px, W1[0*L+l] + W1[6*L+l], a);
        a = fmaf(py, W1[1*L+l] + W1[7*L+l], a);
        a = fmaf(pz, W1[2*L+l] + W1[8*L+l], a);
        g_A[idx] = a;
        return;
    }
    idx -= NQ * L;
    if (idx < NO * L) {                       // B
        int o = idx >> 6, l = idx & 63;
        float px = pos_o[o*3+0], py = pos_o[o*3+1], pz = pos_o[o*3+2];
        float b =      px * (W1[3*L+l] - W1[6*L+l]);
        b = fmaf(py, W1[4*L+l] - W1[7*L+l], b);
        b = fmaf(pz, W1[5*L+l] - W1[8*L+l], b);
        g_B[idx] = b;
    }
}

// ------------------------------------------------------------------
// Main pairwise kernel — EXACT R6 structure and inner loop (the best
// measured config): one thread = one Morton-sorted query, one obs
// chunk per block, occupancy 2, TWO logit accumulators only (adding
// live state here regresses: R8/R10/R11). Packed f32x2 math;
// relu(x)*w == (x+|x|)*(w/2) exactly. Warp (32 spatially local
// queries) skips obs where every lane is outside the radius.
// ------------------------------------------------------------------
__global__ void __launch_bounds__(TPB, 2)
main_kernel(const float* __restrict__ pos_o,
            const float* __restrict__ W2,
            int NQ, int NO)
{
    __shared__ ulonglong2 Bs[CHUNK][16];   // 64 floats/row as 16x ulonglong2
    __shared__ ulonglong2 Vs[CHUNK][16];
    __shared__ ull        W2s[32];         // packed 0.5*W2
    __shared__ float      Ps[CHUNK * 3];

    const int tid = threadIdx.x;
    const int o0  = blockIdx.y * CHUNK;
    const int cnt = min(CHUNK, NO - o0);

    for (int i = tid; i < cnt * 16; i += TPB) {
        int j = i >> 4, c = i & 15;
        Bs[j][c] = reinterpret_cast<const ulonglong2*>(g_B)[(o0 + j) * 16 + c];
        Vs[j][c] = reinterpret_cast<const ulonglong2*>(g_V)[(o0 + j) * 16 + c];
    }
    for (int i = tid; i < cnt * 3; i += TPB)
        Ps[i] = pos_o[o0 * 3 + i];
    if (tid < 32)
        W2s[tid] = pack2(0.5f * W2[2*tid], 0.5f * W2[2*tid + 1]);
    __syncthreads();

    int srt = blockIdx.x * TPB + tid;
    if (srt >= NQ) srt = NQ - 1;           // keep full warps; duplicate writes identical
    const int q = g_perm[srt];
    const float4 pq = g_PQ[srt];

    ull Aq[32];
    #pragma unroll
    for (int c = 0; c < 16; c++) {
        ulonglong2 t = reinterpret_cast<const ulonglong2*>(g_A)[q * 16 + c];
        Aq[2*c] = t.x; Aq[2*c+1] = t.y;
    }
    ull acc[32];
    #pragma unroll
    for (int c = 0; c < 32; c++) acc[c] = 0ull;
    float ssum = 0.f;

    const ull ABSM = 0x7FFFFFFF7FFFFFFFull;

    for (int j = 0; j < cnt; j++) {
        const float dx = pq.x - Ps[3*j+0];
        const float dy = pq.y - Ps[3*j+1];
        const float dz = pq.z - Ps[3*j+2];
        const float d2 = fmaf(dx, dx, fmaf(dy, dy, dz * dz));
        if (__all_sync(0xFFFFFFFFu, d2 > 0.25f)) continue;

        ull lg0 = 0ull, lg1 = 0ull;
        #pragma unroll
        for (int c = 0; c < 16; c++) {
            const ulonglong2 b = Bs[j][c];
            const ull w0 = W2s[2*c], w1 = W2s[2*c+1];
            ull x0 = pk_add(Aq[2*c],   b.x);
            ull x1 = pk_add(Aq[2*c+1], b.y);
            ull r0 = pk_add(x0, x0 & ABSM);     // 2*relu(x)
            ull r1 = pk_add(x1, x1 & ABSM);
            lg0 = pk_fma(r0, w0, lg0);
            lg1 = pk_fma(r1, w1, lg1);
        }
        float2 s0 = unpack2(lg0), s1 = unpack2(lg1);
        const float lg = (s0.x + s0.y) + (s1.x + s1.y);
        const float wgt = (d2 <= 0.25f) ? __expf(lg) : 0.f;
        ssum += wgt;
        const ull wp = pack2(wgt, wgt);
        #pragma unroll
        for (int c = 0; c < 16; c++) {
            const ulonglong2 v = Vs[j][c];
            acc[2*c]   = pk_fma(wp, v.x, acc[2*c]);
            acc[2*c+1] = pk_fma(wp, v.y, acc[2*c+1]);
        }
    }

    // partials keyed by ORIGINAL query index
    g_psum[blockIdx.y * MAXQ + q] = ssum;
    ulonglong2* pa = reinterpret_cast<ulonglong2*>(
        &g_pacc[((size_t)blockIdx.y * MAXQ + q) * L]);
    #pragma unroll
    for (int c = 0; c < 16; c++)
        pa[c] = make_ulonglong2(acc[2*c], acc[2*c+1]);
}

// ------------------------------------------------------------------
// Combine partial sets: out[q,l] = (sum_c acc) / (sum_c s)
// One thread per float4 output group; dual accumulators.
// ------------------------------------------------------------------
__global__ void reduce_kernel(float* __restrict__ out, int NQ, int nch)
{
    int idx = blockIdx.x * blockDim.x + threadIdx.x;   // float4 granularity
    if (idx >= NQ * 16) return;
    const int q = idx >> 4;
    const int g = idx & 15;

    float s = 0.f;
    for (int c = 0; c < nch; c++) s += g_psum[c * MAXQ + q];

    const float4* pa = reinterpret_cast<const float4*>(g_pacc);
    float4 a0 = make_float4(0.f, 0.f, 0.f, 0.f);
    float4 a1 = make_float4(0.f, 0.f, 0.f, 0.f);
    for (int c = 0; c + 1 < nch; c += 2) {
        float4 t0 = pa[((size_t)(c    ) * MAXQ + q) * 16 + g];
        float4 t1 = pa[((size_t)(c + 1) * MAXQ + q) * 16 + g];
        a0.x += t0.x; a0.y += t0.y; a0.z += t0.z; a0.w += t0.w;
        a1.x += t1.x; a1.y += t1.y; a1.z += t1.z; a1.w += t1.w;
    }
    if (nch & 1) {
        float4 t = pa[((size_t)(nch - 1) * MAXQ + q) * 16 + g];
        a0.x += t.x; a0.y += t.y; a0.z += t.z; a0.w += t.w;
    }
    const float inv = 1.f / s;
    float4 r;
    r.x = (a0.x + a1.x) * inv;
    r.y = (a0.y + a1.y) * inv;
    r.z = (a0.z + a1.z) * inv;
    r.w = (a0.w + a1.w) * inv;
    reinterpret_cast<float4*>(out)[idx] = r;
}

// ------------------------------------------------------------------
extern "C" void kernel_launch(void* const* d_in, const int* in_sizes, int n_in,
                              void* d_out, int out_size)
{
    const float* h_obs     = (const float*)d_in[0];
    // d_in[1] = x_obs (unused by the reference computation)
    const float* pos_obs   = (const float*)d_in[2];
    const float* pos_query = (const float*)d_in[3];
    const float* W1        = (const float*)d_in[4];
    const float* b1        = (const float*)d_in[5];
    const float* W2        = (const float*)d_in[6];
    // d_in[7] = b2 (constant shift, cancels in softmax)
    const float* Wv        = (const float*)d_in[8];
    const float* bv        = (const float*)d_in[9];

    const int NO = in_sizes[2] / 3;
    const int NQ = in_sizes[3] / 3;

    // fused sort (block 0) + prep (blocks 1..)
    const int prep_items = NQ * L + NO * L + NO * 32;
    const int setup_blocks = 1 + (prep_items + 511) / 512;
    setup_kernel<<<setup_blocks, 512>>>(pos_query, pos_obs, h_obs,
                                        W1, b1, Wv, bv, NQ, NO);

    const int nch = (NO + CHUNK - 1) / CHUNK;   // partial sets (=32)
    dim3 grid((NQ + TPB - 1) / TPB, nch);
    main_kernel<<<grid, TPB>>>(pos_obs, W2, NQ, NO);

    reduce_kernel<<<(NQ * 16 + 255) / 256, 256>>>((float*)d_out, NQ, nch);
}

// round 14
// speedup vs baseline: 1.3518x; 1.0032x over previous
#include <cuda_runtime.h>

#define L        64
#define CHUNK    64
#define TPB      128
#define MAXQ     2048
#define MAXCH    32

typedef unsigned long long ull;

// ---- scratch ( __device__ globals: allocation-free ) ----
__device__ __align__(16) float g_A[MAXQ * L];        // per-query affine part, ORIGINAL order
__device__ __align__(16) float g_As[MAXQ * L];       // per-query affine part, SORTED order
__device__ __align__(16) float g_B[MAXQ * L];        // per-obs affine part
__device__ __align__(16) float g_V[MAXQ * L];        // value-projected h_obs
__device__ float4 g_PQ[MAXQ];                        // query positions, SORTED order
__device__ int    g_perm[MAXQ];                      // sorted slot -> original query idx
__device__ float  g_psum[MAXCH * MAXQ];              // partial weight sums  (original q)
__device__ __align__(16) float g_pacc[MAXCH * MAXQ * L];  // partial value sums (original q)

// ---- packed f32x2 helpers ----
__device__ __forceinline__ ull pk_add(ull a, ull b) {
    ull r; asm("add.rn.f32x2 %0,%1,%2;" : "=l"(r) : "l"(a), "l"(b)); return r;
}
__device__ __forceinline__ ull pk_fma(ull a, ull b, ull c) {
    ull r; asm("fma.rn.f32x2 %0,%1,%2,%3;" : "=l"(r) : "l"(a), "l"(b), "l"(c)); return r;
}
union PK { ull u; float2 f; };
__device__ __forceinline__ ull pack2(float x, float y) { PK p; p.f.x = x; p.f.y = y; return p.u; }
__device__ __forceinline__ float2 unpack2(ull u) { PK p; p.u = u; return p.f; }

// ------------------------------------------------------------------
// Fused setup. Block 0: Morton counting sort of queries (8x8x8 cells)
// -> g_perm + g_PQ. Blocks >= 1 (branch-pure per block; region sizes
// are multiples of 512):
//   A[q,l] = b1[l] + pos_q[q] . (W1[0:3]+W1[6:9])        (ORIGINAL order)
//   B[o,l] =         pos_o[o] . (W1[3:6]-W1[6:9])
//   V[o,:] = bv + h_obs[o] @ Wv          (packed f32x2, Wv staged in smem)
// Sort scatter order is atomic-nondeterministic, but downstream math is
// keyed by original q and thread-assignment independent -> bitwise
// deterministic output.
// ------------------------------------------------------------------
__global__ void setup_kernel(const float* __restrict__ pos_q,
                             const float* __restrict__ pos_o,
                             const float* __restrict__ h_obs,
                             const float* __restrict__ W1,
                             const float* __restrict__ b1,
                             const float* __restrict__ Wv,
                             const float* __restrict__ bv,
                             int NQ, int NO)
{
    if (blockIdx.x == 0) {
        __shared__ int cid[MAXQ];
        __shared__ int hist[512];
        __shared__ int scanA[512];
        __shared__ int scanB[512];
        const int t = threadIdx.x;            // blockDim = 512
        hist[t] = 0;
        __syncthreads();

        for (int i = t; i < NQ; i += 512) {
            float x = pos_q[3*i], y = pos_q[3*i+1], z = pos_q[3*i+2];
            int xc = min(7, max(0, (int)(x * 8.f)));
            int yc = min(7, max(0, (int)(y * 8.f)));
            int zc = min(7, max(0, (int)(z * 8.f)));
            int m = 0;
            #pragma unroll
            for (int b = 0; b < 3; b++)
                m |= (((xc >> b) & 1) << (3*b)) | (((yc >> b) & 1) << (3*b + 1))
                   | (((zc >> b) & 1) << (3*b + 2));
            cid[i] = m;
            atomicAdd(&hist[m], 1);
        }
        __syncthreads();

        scanA[t] = hist[t];
        __syncthreads();
        int* src = scanA; int* dst = scanB;
        for (int d = 1; d < 512; d <<= 1) {
            dst[t] = src[t] + ((t >= d) ? src[t - d] : 0);
            __syncthreads();
            int* tmp = src; src = dst; dst = tmp;
        }
        src[t] -= hist[t];                    // exclusive offsets, in place
        __syncthreads();

        for (int i = t; i < NQ; i += 512) {
            int p = atomicAdd(&src[cid[i]], 1);
            g_perm[p] = i;
            g_PQ[p] = make_float4(pos_q[3*i], pos_q[3*i+1], pos_q[3*i+2], 0.f);
        }
        return;
    }

    const int base = (blockIdx.x - 1) * 512;

    // ---- V branch: whole block lives in this region (offsets are 512-mult)
    if (base >= NQ * L + NO * L) {
        __shared__ ull WvS[L * 32];           // 64x64 floats = 2048 ull = 16KB
        const ull* WvP = reinterpret_cast<const ull*>(Wv);
        for (int i = threadIdx.x; i < L * 32; i += 512)
            WvS[i] = WvP[i];
        __syncthreads();

        int idx = base + threadIdx.x - (NQ * L + NO * L);
        if (idx >= NO * 32) return;
        int o = idx >> 5, lp = idx & 31;
        const float4* h4 = reinterpret_cast<const float4*>(h_obs + o * L);
        float2 bvp = reinterpret_cast<const float2*>(bv)[lp];
        ull a0 = pack2(bvp.x, bvp.y), a1 = 0ull, a2 = 0ull, a3 = 0ull;
        #pragma unroll
        for (int k = 0; k < 16; k++) {
            float4 h = h4[k];
            a0 = pk_fma(pack2(h.x, h.x), WvS[(4*k+0)*32 + lp], a0);
            a1 = pk_fma(pack2(h.y, h.y), WvS[(4*k+1)*32 + lp], a1);
            a2 = pk_fma(pack2(h.z, h.z), WvS[(4*k+2)*32 + lp], a2);
            a3 = pk_fma(pack2(h.w, h.w), WvS[(4*k+3)*32 + lp], a3);
        }
        reinterpret_cast<ull*>(g_V)[o*32 + lp] = pk_add(pk_add(a0, a1), pk_add(a2, a3));
        return;
    }

    int idx = base + threadIdx.x;
    if (idx < NQ * L) {                       // A, original order
        int q = idx >> 6, l = idx & 63;
        float px = pos_q[q*3+0], py = pos_q[q*3+1], pz = pos_q[q*3+2];
        float a = b1[l];
        a = fmaf(px, W1[0*L+l] + W1[6*L+l], a);
        a = fmaf(py, W1[1*L+l] + W1[7*L+l], a);
        a = fmaf(pz, W1[2*L+l] + W1[8*L+l], a);
        g_A[idx] = a;
        return;
    }
    idx -= NQ * L;
    if (idx < NO * L) {                       // B
        int o = idx >> 6, l = idx & 63;
        float px = pos_o[o*3+0], py = pos_o[o*3+1], pz = pos_o[o*3+2];
        float b =      px * (W1[3*L+l] - W1[6*L+l]);
        b = fmaf(py, W1[4*L+l] - W1[7*L+l], b);
        b = fmaf(pz, W1[5*L+l] - W1[8*L+l], b);
        g_B[idx] = b;
    }
}

// ------------------------------------------------------------------
// Permute A into sorted order (runs after setup; coalesced in 256B
// segments: 16 consecutive threads copy one row).
// ------------------------------------------------------------------
__global__ void permA_kernel(int NQ)
{
    int idx = blockIdx.x * blockDim.x + threadIdx.x;   // float4 granularity
    if (idx >= NQ * 16) return;
    const int srt = idx >> 4, c = idx & 15;
    const int q = g_perm[srt];
    reinterpret_cast<float4*>(g_As)[idx] =
        reinterpret_cast<const float4*>(g_A)[q * 16 + c];
}

// ------------------------------------------------------------------
// Main pairwise kernel — R6 structure (one thread = one sorted query,
// occupancy 2, TWO logit accumulators; adding live state regresses:
// R8/R10/R11) with two changes:
//   * Aq loaded COALESCED from g_As (sorted order)
//   * acc application software-pipelined one obs behind the logit
//     chain, hiding the logit-reduce -> expf -> acc serial junction.
// Packed f32x2 math; relu(x)*w == (x+|x|)*(w/2) exactly. Warp (32
// spatially local queries) skips obs where every lane is outside the
// radius.
// ------------------------------------------------------------------
__global__ void __launch_bounds__(TPB, 2)
main_kernel(const float* __restrict__ pos_o,
            const float* __restrict__ W2,
            int NQ, int NO)
{
    __shared__ ulonglong2 Bs[CHUNK][16];   // 64 floats/row as 16x ulonglong2
    __shared__ ulonglong2 Vs[CHUNK][16];
    __shared__ ull        W2s[32];         // packed 0.5*W2
    __shared__ float      Ps[CHUNK * 3];

    const int tid = threadIdx.x;
    const int o0  = blockIdx.y * CHUNK;
    const int cnt = min(CHUNK, NO - o0);

    for (int i = tid; i < cnt * 16; i += TPB) {
        int j = i >> 4, c = i & 15;
        Bs[j][c] = reinterpret_cast<const ulonglong2*>(g_B)[(o0 + j) * 16 + c];
        Vs[j][c] = reinterpret_cast<const ulonglong2*>(g_V)[(o0 + j) * 16 + c];
    }
    for (int i = tid; i < cnt * 3; i += TPB)
        Ps[i] = pos_o[o0 * 3 + i];
    if (tid < 32)
        W2s[tid] = pack2(0.5f * W2[2*tid], 0.5f * W2[2*tid + 1]);
    __syncthreads();

    int srt = blockIdx.x * TPB + tid;
    if (srt >= NQ) srt = NQ - 1;           // keep full warps; duplicate writes identical
    const float4 pq = g_PQ[srt];

    ull Aq[32];
    #pragma unroll
    for (int c = 0; c < 16; c++) {
        ulonglong2 t = reinterpret_cast<const ulonglong2*>(g_As)[srt * 16 + c];
        Aq[2*c] = t.x; Aq[2*c+1] = t.y;
    }
    ull acc[32];
    #pragma unroll
    for (int c = 0; c < 32; c++) acc[c] = 0ull;
    float ssum = 0.f;

    const ull ABSM = 0x7FFFFFFF7FFFFFFFull;

    // software pipeline: pending (weight, obs index); starts as a
    // harmless no-op (weight 0 applied to row 0: acc += 0*V == acc).
    float pw = 0.f;
    int   pj = 0;

    for (int j = 0; j < cnt; j++) {
        const float dx = pq.x - Ps[3*j+0];
        const float dy = pq.y - Ps[3*j+1];
        const float dz = pq.z - Ps[3*j+2];
        const float d2 = fmaf(dx, dx, fmaf(dy, dy, dz * dz));
        if (__all_sync(0xFFFFFFFFu, d2 > 0.25f)) continue;

        ull lg0 = 0ull, lg1 = 0ull;
        #pragma unroll
        for (int c = 0; c < 16; c++) {
            const ulonglong2 b = Bs[j][c];
            const ull w0 = W2s[2*c], w1 = W2s[2*c+1];
            ull x0 = pk_add(Aq[2*c],   b.x);
            ull x1 = pk_add(Aq[2*c+1], b.y);
            ull r0 = pk_add(x0, x0 & ABSM);     // 2*relu(x)
            ull r1 = pk_add(x1, x1 & ABSM);
            lg0 = pk_fma(r0, w0, lg0);
            lg1 = pk_fma(r1, w1, lg1);
        }
        // apply the PREVIOUS surviving obs while this one's logit/expf
        // chain completes
        {
            const ull wp = pack2(pw, pw);
            #pragma unroll
            for (int c = 0; c < 16; c++) {
                const ulonglong2 v = Vs[pj][c];
                acc[2*c]   = pk_fma(wp, v.x, acc[2*c]);
                acc[2*c+1] = pk_fma(wp, v.y, acc[2*c+1]);
            }
        }
        float2 s0 = unpack2(lg0), s1 = unpack2(lg1);
        const float lg = (s0.x + s0.y) + (s1.x + s1.y);
        const float wgt = (d2 <= 0.25f) ? __expf(lg) : 0.f;
        ssum += wgt;
        pw = wgt;
        pj = j;
    }
    // drain the pipeline
    {
        const ull wp = pack2(pw, pw);
        #pragma unroll
        for (int c = 0; c < 16; c++) {
            const ulonglong2 v = Vs[pj][c];
            acc[2*c]   = pk_fma(wp, v.x, acc[2*c]);
            acc[2*c+1] = pk_fma(wp, v.y, acc[2*c+1]);
        }
    }

    // partials keyed by ORIGINAL query index
    const int q = g_perm[srt];
    g_psum[blockIdx.y * MAXQ + q] = ssum;
    ulonglong2* pa = reinterpret_cast<ulonglong2*>(
        &g_pacc[((size_t)blockIdx.y * MAXQ + q) * L]);
    #pragma unroll
    for (int c = 0; c < 16; c++)
        pa[c] = make_ulonglong2(acc[2*c], acc[2*c+1]);
}

// ------------------------------------------------------------------
// Combine partial sets: out[q,l] = (sum_c acc) / (sum_c s)
// One thread per float4 output group; dual accumulators.
// ------------------------------------------------------------------
__global__ void reduce_kernel(float* __restrict__ out, int NQ, int nch)
{
    int idx = blockIdx.x * blockDim.x + threadIdx.x;   // float4 granularity
    if (idx >= NQ * 16) return;
    const int q = idx >> 4;
    const int g = idx & 15;

    float s = 0.f;
    for (int c = 0; c < nch; c++) s += g_psum[c * MAXQ + q];

    const float4* pa = reinterpret_cast<const float4*>(g_pacc);
    float4 a0 = make_float4(0.f, 0.f, 0.f, 0.f);
    float4 a1 = make_float4(0.f, 0.f, 0.f, 0.f);
    for (int c = 0; c + 1 < nch; c += 2) {
        float4 t0 = pa[((size_t)(c    ) * MAXQ + q) * 16 + g];
        float4 t1 = pa[((size_t)(c + 1) * MAXQ + q) * 16 + g];
        a0.x += t0.x; a0.y += t0.y; a0.z += t0.z; a0.w += t0.w;
        a1.x += t1.x; a1.y += t1.y; a1.z += t1.z; a1.w += t1.w;
    }
    if (nch & 1) {
        float4 t = pa[((size_t)(nch - 1) * MAXQ + q) * 16 + g];
        a0.x += t.x; a0.y += t.y; a0.z += t.z; a0.w += t.w;
    }
    const float inv = 1.f / s;
    float4 r;
    r.x = (a0.x + a1.x) * inv;
    r.y = (a0.y + a1.y) * inv;
    r.z = (a0.z + a1.z) * inv;
    r.w = (a0.w + a1.w) * inv;
    reinterpret_cast<float4*>(out)[idx] = r;
}

// ------------------------------------------------------------------
extern "C" void kernel_launch(void* const* d_in, const int* in_sizes, int n_in,
                              void* d_out, int out_size)
{
    const float* h_obs     = (const float*)d_in[0];
    // d_in[1] = x_obs (unused by the reference computation)
    const float* pos_obs   = (const float*)d_in[2];
    const float* pos_query = (const float*)d_in[3];
    const float* W1        = (const float*)d_in[4];
    const float* b1        = (const float*)d_in[5];
    const float* W2        = (const float*)d_in[6];
    // d_in[7] = b2 (constant shift, cancels in softmax)
    const float* Wv        = (const float*)d_in[8];
    const float* bv        = (const float*)d_in[9];

    const int NO = in_sizes[2] / 3;
    const int NQ = in_sizes[3] / 3;

    // fused sort (block 0) + prep (blocks 1..)
    const int prep_items = NQ * L + NO * L + NO * 32;
    const int setup_blocks = 1 + (prep_items + 511) / 512;
    setup_kernel<<<setup_blocks, 512>>>(pos_query, pos_obs, h_obs,
                                        W1, b1, Wv, bv, NQ, NO);

    permA_kernel<<<(NQ * 16 + 255) / 256, 256>>>(NQ);

    const int nch = (NO + CHUNK - 1) / CHUNK;   // partial sets (=32)
    dim3 grid((NQ + TPB - 1) / TPB, nch);
    main_kernel<<<grid, TPB>>>(pos_obs, W2, NQ, NO);

    reduce_kernel<<<(NQ * 16 + 255) / 256, 256>>>((float*)d_out, NQ, nch);
}

// round 17
// speedup vs baseline: 1.4278x; 1.0562x over previous
#include <cuda_runtime.h>

#define L        64
#define CHUNK    64
#define TPB      128
#define MAXQ     2048
#define MAXCH    32

typedef unsigned long long ull;

// ---- scratch ( __device__ globals: allocation-free ) ----
__device__ __align__(16) float g_A[MAXQ * L];        // per-query affine part, ORIGINAL order
__device__ __align__(16) float g_As[MAXQ * L];       // per-query affine part, SORTED order
__device__ __align__(16) float g_B[MAXQ * L];        // per-obs affine part
__device__ __align__(16) float g_V[MAXQ * L];        // value-projected h_obs
__device__ float4 g_PQ[MAXQ];                        // query positions, SORTED order
__device__ int    g_perm[MAXQ];                      // sorted slot -> original query idx
__device__ float  g_psum[MAXCH * MAXQ];              // partial weight sums  (original q)
__device__ __align__(16) float g_pacc[MAXCH * MAXQ * L];  // partial value sums (original q)

// ---- packed f32x2 helpers ----
__device__ __forceinline__ ull pk_add(ull a, ull b) {
    ull r; asm("add.rn.f32x2 %0,%1,%2;" : "=l"(r) : "l"(a), "l"(b)); return r;
}
__device__ __forceinline__ ull pk_fma(ull a, ull b, ull c) {
    ull r; asm("fma.rn.f32x2 %0,%1,%2,%3;" : "=l"(r) : "l"(a), "l"(b), "l"(c)); return r;
}
union PK { ull u; float2 f; };
__device__ __forceinline__ ull pack2(float x, float y) { PK p; p.f.x = x; p.f.y = y; return p.u; }
__device__ __forceinline__ float2 unpack2(ull u) { PK p; p.u = u; return p.f; }

// ------------------------------------------------------------------
// Fused setup. Block 0: Morton counting sort of queries (8x8x8 cells)
// -> g_perm + g_PQ. Blocks >= 1 (branch-pure per block; region sizes
// are multiples of 512):
//   A[q,l] = b1[l] + pos_q[q] . (W1[0:3]+W1[6:9])        (ORIGINAL order)
//   B[o,l] =         pos_o[o] . (W1[3:6]-W1[6:9])
//   V[o,:] = bv + h_obs[o] @ Wv          (packed f32x2, Wv staged in smem)
// Sort scatter order is atomic-nondeterministic, but downstream math is
// keyed by original q and thread-assignment independent -> bitwise
// deterministic output.
// ------------------------------------------------------------------
__global__ void setup_kernel(const float* __restrict__ pos_q,
                             const float* __restrict__ pos_o,
                             const float* __restrict__ h_obs,
                             const float* __restrict__ W1,
                             const float* __restrict__ b1,
                             const float* __restrict__ Wv,
                             const float* __restrict__ bv,
                             int NQ, int NO)
{
    if (blockIdx.x == 0) {
        __shared__ int cid[MAXQ];
        __shared__ int hist[512];
        __shared__ int scanA[512];
        __shared__ int scanB[512];
        const int t = threadIdx.x;            // blockDim = 512
        hist[t] = 0;
        __syncthreads();

        for (int i = t; i < NQ; i += 512) {
            float x = pos_q[3*i], y = pos_q[3*i+1], z = pos_q[3*i+2];
            int xc = min(7, max(0, (int)(x * 8.f)));
            int yc = min(7, max(0, (int)(y * 8.f)));
            int zc = min(7, max(0, (int)(z * 8.f)));
            int m = 0;
            #pragma unroll
            for (int b = 0; b < 3; b++)
                m |= (((xc >> b) & 1) << (3*b)) | (((yc >> b) & 1) << (3*b + 1))
                   | (((zc >> b) & 1) << (3*b + 2));
            cid[i] = m;
            atomicAdd(&hist[m], 1);
        }
        __syncthreads();

        scanA[t] = hist[t];
        __syncthreads();
        int* src = scanA; int* dst = scanB;
        for (int d = 1; d < 512; d <<= 1) {
            dst[t] = src[t] + ((t >= d) ? src[t - d] : 0);
            __syncthreads();
            int* tmp = src; src = dst; dst = tmp;
        }
        src[t] -= hist[t];                    // exclusive offsets, in place
        __syncthreads();

        for (int i = t; i < NQ; i += 512) {
            int p = atomicAdd(&src[cid[i]], 1);
            g_perm[p] = i;
            g_PQ[p] = make_float4(pos_q[3*i], pos_q[3*i+1], pos_q[3*i+2], 0.f);
        }
        return;
    }

    const int base = (blockIdx.x - 1) * 512;

    // ---- V branch: whole block lives in this region (offsets are 512-mult)
    if (base >= NQ * L + NO * L) {
        __shared__ ull WvS[L * 32];           // 64x64 floats = 2048 ull = 16KB
        const ull* WvP = reinterpret_cast<const ull*>(Wv);
        for (int i = threadIdx.x; i < L * 32; i += 512)
            WvS[i] = WvP[i];
        __syncthreads();

        int idx = base + threadIdx.x - (NQ * L + NO * L);
        if (idx >= NO * 32) return;
        int o = idx >> 5, lp = idx & 31;
        const float4* h4 = reinterpret_cast<const float4*>(h_obs + o * L);
        float2 bvp = reinterpret_cast<const float2*>(bv)[lp];
        ull a0 = pack2(bvp.x, bvp.y), a1 = 0ull, a2 = 0ull, a3 = 0ull;
        #pragma unroll
        for (int k = 0; k < 16; k++) {
            float4 h = h4[k];
            a0 = pk_fma(pack2(h.x, h.x), WvS[(4*k+0)*32 + lp], a0);
            a1 = pk_fma(pack2(h.y, h.y), WvS[(4*k+1)*32 + lp], a1);
            a2 = pk_fma(pack2(h.z, h.z), WvS[(4*k+2)*32 + lp], a2);
            a3 = pk_fma(pack2(h.w, h.w), WvS[(4*k+3)*32 + lp], a3);
        }
        reinterpret_cast<ull*>(g_V)[o*32 + lp] = pk_add(pk_add(a0, a1), pk_add(a2, a3));
        return;
    }

    int idx = base + threadIdx.x;
    if (idx < NQ * L) {                       // A, original order
        int q = idx >> 6, l = idx & 63;
        float px = pos_q[q*3+0], py = pos_q[q*3+1], pz = pos_q[q*3+2];
        float a = b1[l];
        a = fmaf(px, W1[0*L+l] + W1[6*L+l], a);
        a = fmaf(py, W1[1*L+l] + W1[7*L+l], a);
        a = fmaf(pz, W1[2*L+l] + W1[8*L+l], a);
        g_A[idx] = a;
        return;
    }
    idx -= NQ * L;
    if (idx < NO * L) {                       // B
        int o = idx >> 6, l = idx & 63;
        float px = pos_o[o*3+0], py = pos_o[o*3+1], pz = pos_o[o*3+2];
        float b =      px * (W1[3*L+l] - W1[6*L+l]);
        b = fmaf(py, W1[4*L+l] - W1[7*L+l], b);
        b = fmaf(pz, W1[5*L+l] - W1[8*L+l], b);
        g_B[idx] = b;
    }
}

// ------------------------------------------------------------------
// Permute A into sorted order (runs after setup; coalesced in 256B
// segments: 16 consecutive threads copy one row).
// ------------------------------------------------------------------
__global__ void permA_kernel(int NQ)
{
    int idx = blockIdx.x * blockDim.x + threadIdx.x;   // float4 granularity
    if (idx >= NQ * 16) return;
    const int srt = idx >> 4, c = idx & 15;
    const int q = g_perm[srt];
    reinterpret_cast<float4*>(g_As)[idx] =
        reinterpret_cast<const float4*>(g_A)[q * 16 + c];
}

// ------------------------------------------------------------------
// Main pairwise kernel — UNCHANGED from R14 (measured main ~45us):
// one thread = one sorted query, occupancy 2, two logit accumulators,
// coalesced sorted-A load, acc application software-pipelined one obs
// behind the logit/expf chain. Packed f32x2; relu(x)*w==(x+|x|)*(w/2).
// ------------------------------------------------------------------
__global__ void __launch_bounds__(TPB, 2)
main_kernel(const float* __restrict__ pos_o,
            const float* __restrict__ W2,
            int NQ, int NO)
{
    __shared__ ulonglong2 Bs[CHUNK][16];   // 64 floats/row as 16x ulonglong2
    __shared__ ulonglong2 Vs[CHUNK][16];
    __shared__ ull        W2s[32];         // packed 0.5*W2
    __shared__ float      Ps[CHUNK * 3];

    const int tid = threadIdx.x;
    const int o0  = blockIdx.y * CHUNK;
    const int cnt = min(CHUNK, NO - o0);

    for (int i = tid; i < cnt * 16; i += TPB) {
        int j = i >> 4, c = i & 15;
        Bs[j][c] = reinterpret_cast<const ulonglong2*>(g_B)[(o0 + j) * 16 + c];
        Vs[j][c] = reinterpret_cast<const ulonglong2*>(g_V)[(o0 + j) * 16 + c];
    }
    for (int i = tid; i < cnt * 3; i += TPB)
        Ps[i] = pos_o[o0 * 3 + i];
    if (tid < 32)
        W2s[tid] = pack2(0.5f * W2[2*tid], 0.5f * W2[2*tid + 1]);
    __syncthreads();

    int srt = blockIdx.x * TPB + tid;
    if (srt >= NQ) srt = NQ - 1;           // keep full warps; duplicate writes identical
    const float4 pq = g_PQ[srt];

    ull Aq[32];
    #pragma unroll
    for (int c = 0; c < 16; c++) {
        ulonglong2 t = reinterpret_cast<const ulonglong2*>(g_As)[srt * 16 + c];
        Aq[2*c] = t.x; Aq[2*c+1] = t.y;
    }
    ull acc[32];
    #pragma unroll
    for (int c = 0; c < 32; c++) acc[c] = 0ull;
    float ssum = 0.f;

    const ull ABSM = 0x7FFFFFFF7FFFFFFFull;

    // software pipeline: pending (weight, obs index); starts as a
    // harmless no-op (weight 0 applied to row 0: acc += 0*V == acc).
    float pw = 0.f;
    int   pj = 0;

    for (int j = 0; j < cnt; j++) {
        const float dx = pq.x - Ps[3*j+0];
        const float dy = pq.y - Ps[3*j+1];
        const float dz = pq.z - Ps[3*j+2];
        const float d2 = fmaf(dx, dx, fmaf(dy, dy, dz * dz));
        if (__all_sync(0xFFFFFFFFu, d2 > 0.25f)) continue;

        ull lg0 = 0ull, lg1 = 0ull;
        #pragma unroll
        for (int c = 0; c < 16; c++) {
            const ulonglong2 b = Bs[j][c];
            const ull w0 = W2s[2*c], w1 = W2s[2*c+1];
            ull x0 = pk_add(Aq[2*c],   b.x);
            ull x1 = pk_add(Aq[2*c+1], b.y);
            ull r0 = pk_add(x0, x0 & ABSM);     // 2*relu(x)
            ull r1 = pk_add(x1, x1 & ABSM);
            lg0 = pk_fma(r0, w0, lg0);
            lg1 = pk_fma(r1, w1, lg1);
        }
        // apply the PREVIOUS surviving obs while this one's logit/expf
        // chain completes
        {
            const ull wp = pack2(pw, pw);
            #pragma unroll
            for (int c = 0; c < 16; c++) {
                const ulonglong2 v = Vs[pj][c];
                acc[2*c]   = pk_fma(wp, v.x, acc[2*c]);
                acc[2*c+1] = pk_fma(wp, v.y, acc[2*c+1]);
            }
        }
        float2 s0 = unpack2(lg0), s1 = unpack2(lg1);
        const float lg = (s0.x + s0.y) + (s1.x + s1.y);
        const float wgt = (d2 <= 0.25f) ? __expf(lg) : 0.f;
        ssum += wgt;
        pw = wgt;
        pj = j;
    }
    // drain the pipeline
    {
        const ull wp = pack2(pw, pw);
        #pragma unroll
        for (int c = 0; c < 16; c++) {
            const ulonglong2 v = Vs[pj][c];
            acc[2*c]   = pk_fma(wp, v.x, acc[2*c]);
            acc[2*c+1] = pk_fma(wp, v.y, acc[2*c+1]);
        }
    }

    // partials keyed by ORIGINAL query index
    const int q = g_perm[srt];
    g_psum[blockIdx.y * MAXQ + q] = ssum;
    ulonglong2* pa = reinterpret_cast<ulonglong2*>(
        &g_pacc[((size_t)blockIdx.y * MAXQ + q) * L]);
    #pragma unroll
    for (int c = 0; c < 16; c++)
        pa[c] = make_ulonglong2(acc[2*c], acc[2*c+1]);
}

// ------------------------------------------------------------------
// Combine partial sets: out[q,l] = (sum_c acc) / (sum_c s).
// ONE THREAD PER SCALAR OUTPUT (NQ*L = 131072 threads, 512 blocks):
// 4x the parallelism of the float4 version (which ran only 128 blocks
// and was latency-starved at occ 12%). Loads are coalesced (warp spans
// consecutive l) and independent across c via dual accumulators; psum
// reads are warp-broadcast cache hits.
// ------------------------------------------------------------------
__global__ void reduce_kernel(float* __restrict__ out, int NQ, int nch)
{
    int idx = blockIdx.x * blockDim.x + threadIdx.x;   // scalar granularity
    if (idx >= NQ * L) return;
    const int q = idx >> 6;

    float s0 = 0.f, s1 = 0.f;
    for (int c = 0; c + 1 < nch; c += 2) {
        s0 += g_psum[(c    ) * MAXQ + q];
        s1 += g_psum[(c + 1) * MAXQ + q];
    }
    if (nch & 1) s0 += g_psum[(nch - 1) * MAXQ + q];

    float a0 = 0.f, a1 = 0.f;
    const size_t stride = (size_t)MAXQ * L;
    for (int c = 0; c + 1 < nch; c += 2) {
        a0 += g_pacc[(size_t)(c    ) * stride + idx];
        a1 += g_pacc[(size_t)(c + 1) * stride + idx];
    }
    if (nch & 1) a0 += g_pacc[(size_t)(nch - 1) * stride + idx];

    out[idx] = (a0 + a1) / (s0 + s1);
}

// ------------------------------------------------------------------
extern "C" void kernel_launch(void* const* d_in, const int* in_sizes, int n_in,
                              void* d_out, int out_size)
{
    const float* h_obs     = (const float*)d_in[0];
    // d_in[1] = x_obs (unused by the reference computation)
    const float* pos_obs   = (const float*)d_in[2];
    const float* pos_query = (const float*)d_in[3];
    const float* W1        = (const float*)d_in[4];
    const float* b1        = (const float*)d_in[5];
    const float* W2        = (const float*)d_in[6];
    // d_in[7] = b2 (constant shift, cancels in softmax)
    const float* Wv        = (const float*)d_in[8];
    const float* bv        = (const float*)d_in[9];

    const int NO = in_sizes[2] / 3;
    const int NQ = in_sizes[3] / 3;

    // fused sort (block 0) + prep (blocks 1..)
    const int prep_items = NQ * L + NO * L + NO * 32;
    const int setup_blocks = 1 + (prep_items + 511) / 512;
    setup_kernel<<<setup_blocks, 512>>>(pos_query, pos_obs, h_obs,
                                        W1, b1, Wv, bv, NQ, NO);

    permA_kernel<<<(NQ * 16 + 255) / 256, 256>>>(NQ);

    const int nch = (NO + CHUNK - 1) / CHUNK;   // partial sets (=32)
    dim3 grid((NQ + TPB - 1) / TPB, nch);
    main_kernel<<<grid, TPB>>>(pos_obs, W2, NQ, NO);

    reduce_kernel<<<(NQ * L + 255) / 256, 256>>>((float*)d_out, NQ, nch);
}